// round 2
// baseline (speedup 1.0000x reference)
#include <cuda_runtime.h>
#include <math.h>

#define BB 8
#define LL 4096
#define DM 512
#define DI 1024
#define DXZ 2048
#define NST 16
#define DFF 2048
#define NT (BB*LL)   // 32768 tokens

// ---------------- scratch (allocation-free: __device__ globals) ----------------
__device__ float g_xz [2][(size_t)NT*DXZ];   // in_proj out (xi | z)
__device__ float g_xc [2][(size_t)NT*DI];    // conv+silu out
__device__ float g_dbc[2][(size_t)NT*64];    // x_proj out (dt_low | B | C)
__device__ float g_dt [2][(size_t)NT*DI];    // softplus(dt)
__device__ float g_ys [2][(size_t)NT*DI];    // scan out * silu(z)
__device__ float g_mp [2][(size_t)NT*DM];    // mamba out_proj
__device__ float g_h  [(size_t)NT*DM];       // 0.5*(LN_f + LN_b)
__device__ float g_mid[(size_t)NT*DFF];      // FFN hidden
__device__ float g_ff2[(size_t)NT*DM];       // FFN out

// ---------------- math helpers ----------------
__device__ __forceinline__ float sigmoidf_(float x){ return 1.f/(1.f+__expf(-x)); }
__device__ __forceinline__ float softplusf_(float x){ return fmaxf(x,0.f) + log1pf(__expf(-fabsf(x))); }
__device__ __forceinline__ float geluf_(float x){
    float x3 = x*x*x;
    return 0.5f*x*(1.f + tanhf(0.7978845608028654f*(x + 0.044715f*x3)));
}
__device__ __forceinline__ float warp_sum(float v){
    #pragma unroll
    for (int o=16;o>0;o>>=1) v += __shfl_xor_sync(0xffffffffu, v, o);
    return v;
}

// ---------------- generic SGEMM: C[M,N] = A[M,K](lda) @ B[N,K]^T, fused epilogue ----------------
// epi: 0 none, 1 softplus(+bias), 2 gelu(+bias), 3 +bias
// Requires: M%128==0, N%64==0, K%8==0, lda%4==0 (all true for this problem)
__global__ void __launch_bounds__(256,2)
sgemm(const float* __restrict__ A, const float* __restrict__ B, float* __restrict__ C,
      int N, int K, int lda, const float* __restrict__ bias, int epi)
{
    __shared__ float As[8][132];
    __shared__ float Bs[8][68];
    const int tid = threadIdx.x;
    const int m0 = blockIdx.y*128, n0 = blockIdx.x*64;
    const int tx = tid & 15, ty = tid >> 4;
    const int arow = tid >> 1,          ak = (tid & 1)*4;
    const int brow = (tid & 127) >> 1,  bk = (tid & 1)*4;

    float acc[8][4];
    #pragma unroll
    for (int i=0;i<8;i++)
        #pragma unroll
        for (int j=0;j<4;j++) acc[i][j]=0.f;

    const float* Ap = A + (size_t)(m0+arow)*lda + ak;
    const float* Bp = B + (size_t)(n0+brow)*K  + bk;

    for (int k0=0;k0<K;k0+=8) {
        float4 av = *(const float4*)(Ap + k0);
        float4 bv = make_float4(0.f,0.f,0.f,0.f);
        if (tid < 128) bv = *(const float4*)(Bp + k0);
        __syncthreads();
        As[ak+0][arow]=av.x; As[ak+1][arow]=av.y; As[ak+2][arow]=av.z; As[ak+3][arow]=av.w;
        if (tid < 128) { Bs[bk+0][brow]=bv.x; Bs[bk+1][brow]=bv.y; Bs[bk+2][brow]=bv.z; Bs[bk+3][brow]=bv.w; }
        __syncthreads();
        #pragma unroll
        for (int kk=0; kk<8; kk++) {
            float a[8], b[4];
            *(float4*)(a  ) = *(const float4*)(&As[kk][ty*8  ]);
            *(float4*)(a+4) = *(const float4*)(&As[kk][ty*8+4]);
            *(float4*)(b  ) = *(const float4*)(&Bs[kk][tx*4  ]);
            #pragma unroll
            for (int i=0;i<8;i++)
                #pragma unroll
                for (int j=0;j<4;j++) acc[i][j] = fmaf(a[i], b[j], acc[i][j]);
        }
    }

    #pragma unroll
    for (int i=0;i<8;i++) {
        int m = m0 + ty*8 + i;
        float4 o;
        float* op = (float*)&o;
        #pragma unroll
        for (int j=0;j<4;j++) {
            int n = n0 + tx*4 + j;
            float v = acc[i][j];
            if (epi==1)      v = softplusf_(v + bias[n]);
            else if (epi==2) v = geluf_(v + bias[n]);
            else if (epi==3) v = v + bias[n];
            op[j] = v;
        }
        *(float4*)(C + (size_t)m*N + n0 + tx*4) = o;
    }
}

// ---------------- depthwise causal/anti-causal conv(k=4) + SiLU ----------------
// dir 0: taps l-3..l with w[0..3];  dir 1 (flip-folded): taps l..l+3 with w[3..0]
__global__ void conv_silu(const float* __restrict__ fw, const float* __restrict__ fb,
                          const float* __restrict__ bw, const float* __restrict__ bb)
{
    int dir = blockIdx.y;
    int idx = blockIdx.x*blockDim.x + threadIdx.x;     // over NT*DI
    int d = idx & (DI-1);
    int t = idx >> 10;
    int b = t >> 12, l = t & (LL-1);
    const float* w  = dir ? bw : fw;
    const float* cb = dir ? bb : fb;
    const float* xz = g_xz[dir];
    float acc = cb[d];
    if (!dir) {
        #pragma unroll
        for (int j=0;j<4;j++) {
            int l2 = l-3+j;
            if (l2 >= 0) acc = fmaf(w[d*4+j], xz[((size_t)(b*LL+l2))*DXZ + d], acc);
        }
    } else {
        #pragma unroll
        for (int j=0;j<4;j++) {
            int l2 = l+3-j;
            if (l2 < LL) acc = fmaf(w[d*4+j], xz[((size_t)(b*LL+l2))*DXZ + d], acc);
        }
    }
    g_xc[dir][idx] = acc * sigmoidf_(acc);
}

// ---------------- selective scan: 1 thread per (b,d), 16 states in regs ----------------
__global__ void scan_kernel(const float* __restrict__ AlF, const float* __restrict__ DF,
                            const float* __restrict__ AlB, const float* __restrict__ DB)
{
    int dir = blockIdx.y;
    int gid = blockIdx.x*blockDim.x + threadIdx.x;   // 0..8191
    int b = gid >> 10, d = gid & (DI-1);
    const float* Alog = dir ? AlB : AlF;
    const float* Dp   = dir ? DB  : DF;

    float a[NST];
    #pragma unroll
    for (int n=0;n<NST;n++) a[n] = -__expf(Alog[d*NST+n]);
    float Dd = Dp[d];
    float h[NST];
    #pragma unroll
    for (int n=0;n<NST;n++) h[n] = 0.f;

    const float* dtb = g_dt[dir];
    const float* xcb = g_xc[dir];
    const float* zb  = g_xz[dir];
    const float* bcb = g_dbc[dir];
    float*       yb  = g_ys[dir];

    for (int s=0;s<LL;s++) {
        int l = dir ? (LL-1-s) : s;
        size_t t = (size_t)b*LL + l;
        float dtv = dtb[t*DI + d];
        float xv  = xcb[t*DI + d];
        float zv  = zb [t*DXZ + DI + d];
        const float* bc = bcb + t*64;
        float dx = dtv*xv;
        float y = 0.f;
        #pragma unroll
        for (int n=0;n<NST;n++) {
            float e = __expf(dtv*a[n]);
            h[n] = fmaf(e, h[n], dx*bc[32+n]);
            y = fmaf(h[n], bc[48+n], y);
        }
        y = fmaf(xv, Dd, y);
        y *= zv * sigmoidf_(zv);
        yb[t*DI + d] = y;
    }
}

// ---------------- fused: out_f=LN(x+mf), out_b=LN(x+mb), h=0.5*(of+ob) ----------------
__global__ void ln_mid(const float* __restrict__ x,
                       const float* __restrict__ gf, const float* __restrict__ bf,
                       const float* __restrict__ gb, const float* __restrict__ bb)
{
    int warp = threadIdx.x >> 5, lane = threadIdx.x & 31;
    int row = blockIdx.x*8 + warp;
    const float* xr  = x        + (size_t)row*DM;
    const float* mfr = g_mp[0]  + (size_t)row*DM;
    const float* mbr = g_mp[1]  + (size_t)row*DM;
    float u[16], v[16];
    float su=0.f, sv=0.f, squ=0.f, sqv=0.f;
    #pragma unroll
    for (int i=0;i<16;i++) {
        int c = lane + i*32;
        float xv = xr[c];
        u[i] = xv + mfr[c]; v[i] = xv + mbr[c];
        su += u[i]; sv += v[i];
        squ = fmaf(u[i],u[i],squ); sqv = fmaf(v[i],v[i],sqv);
    }
    su = warp_sum(su); sv = warp_sum(sv);
    squ = warp_sum(squ); sqv = warp_sum(sqv);
    float muu = su*(1.f/DM), mub = sv*(1.f/DM);
    float ru = rsqrtf(squ*(1.f/DM) - muu*muu + 1e-5f);
    float rv = rsqrtf(sqv*(1.f/DM) - mub*mub + 1e-5f);
    #pragma unroll
    for (int i=0;i<16;i++) {
        int c = lane + i*32;
        float of = (u[i]-muu)*ru*gf[c] + bf[c];
        float ob = (v[i]-mub)*rv*gb[c] + bb[c];
        g_h[(size_t)row*DM + c] = 0.5f*(of + ob);
    }
}

// ---------------- final: out = LN(h + ff) ----------------
__global__ void ln_fin(float* __restrict__ out,
                       const float* __restrict__ g, const float* __restrict__ bta)
{
    int warp = threadIdx.x >> 5, lane = threadIdx.x & 31;
    int row = blockIdx.x*8 + warp;
    const float* hr = g_h  + (size_t)row*DM;
    const float* fr = g_ff2 + (size_t)row*DM;
    float u[16];
    float su=0.f, squ=0.f;
    #pragma unroll
    for (int i=0;i<16;i++) {
        int c = lane + i*32;
        u[i] = hr[c] + fr[c];
        su += u[i]; squ = fmaf(u[i],u[i],squ);
    }
    su = warp_sum(su); squ = warp_sum(squ);
    float mu = su*(1.f/DM);
    float r  = rsqrtf(squ*(1.f/DM) - mu*mu + 1e-5f);
    #pragma unroll
    for (int i=0;i<16;i++) {
        int c = lane + i*32;
        out[(size_t)row*DM + c] = (u[i]-mu)*r*g[c] + bta[c];
    }
}

// ---------------- host ----------------
extern "C" void kernel_launch(void* const* d_in, const int* in_sizes, int n_in,
                              void* d_out, int out_size)
{
    const float* x        = (const float*)d_in[0];
    const float* f_in_w   = (const float*)d_in[1];
    const float* f_conv_w = (const float*)d_in[2];
    const float* f_conv_b = (const float*)d_in[3];
    const float* f_xproj_w= (const float*)d_in[4];
    const float* f_dt_w   = (const float*)d_in[5];
    const float* f_dt_b   = (const float*)d_in[6];
    const float* f_A_log  = (const float*)d_in[7];
    const float* f_D      = (const float*)d_in[8];
    const float* f_out_w  = (const float*)d_in[9];
    const float* b_in_w   = (const float*)d_in[10];
    const float* b_conv_w = (const float*)d_in[11];
    const float* b_conv_b = (const float*)d_in[12];
    const float* b_xproj_w= (const float*)d_in[13];
    const float* b_dt_w   = (const float*)d_in[14];
    const float* b_dt_b   = (const float*)d_in[15];
    const float* b_A_log  = (const float*)d_in[16];
    const float* b_D      = (const float*)d_in[17];
    const float* b_out_w  = (const float*)d_in[18];
    const float* ln_f_g   = (const float*)d_in[19];
    const float* ln_f_b   = (const float*)d_in[20];
    const float* ln_b_g   = (const float*)d_in[21];
    const float* ln_b_b   = (const float*)d_in[22];
    const float* ln_ff_g  = (const float*)d_in[23];
    const float* ln_ff_b  = (const float*)d_in[24];
    const float* ffn_w1   = (const float*)d_in[25];
    const float* ffn_b1   = (const float*)d_in[26];
    const float* ffn_w2   = (const float*)d_in[27];
    const float* ffn_b2   = (const float*)d_in[28];

    float *p_xz, *p_xc, *p_dbc, *p_dt, *p_ys, *p_mp, *p_h, *p_mid, *p_ff2;
    cudaGetSymbolAddress((void**)&p_xz , g_xz );
    cudaGetSymbolAddress((void**)&p_xc , g_xc );
    cudaGetSymbolAddress((void**)&p_dbc, g_dbc);
    cudaGetSymbolAddress((void**)&p_dt , g_dt );
    cudaGetSymbolAddress((void**)&p_ys , g_ys );
    cudaGetSymbolAddress((void**)&p_mp , g_mp );
    cudaGetSymbolAddress((void**)&p_h  , g_h  );
    cudaGetSymbolAddress((void**)&p_mid, g_mid);
    cudaGetSymbolAddress((void**)&p_ff2, g_ff2);
    float* xz0 = p_xz;            float* xz1 = p_xz  + (size_t)NT*DXZ;
    float* xc0 = p_xc;            float* xc1 = p_xc  + (size_t)NT*DI;
    float* dbc0= p_dbc;           float* dbc1= p_dbc + (size_t)NT*64;
    float* dt0 = p_dt;            float* dt1 = p_dt  + (size_t)NT*DI;
    float* ys0 = p_ys;            float* ys1 = p_ys  + (size_t)NT*DI;
    float* mp0 = p_mp;            float* mp1 = p_mp  + (size_t)NT*DM;

    // 1) in_proj (both directions; flip is folded into conv/scan)
    sgemm<<<dim3(DXZ/64, NT/128), 256>>>(x, f_in_w, xz0, DXZ, DM, DM, nullptr, 0);
    sgemm<<<dim3(DXZ/64, NT/128), 256>>>(x, b_in_w, xz1, DXZ, DM, DM, nullptr, 0);
    // 2) depthwise conv + SiLU (dir in grid.y)
    conv_silu<<<dim3((NT*DI)/256, 2), 256>>>(f_conv_w, f_conv_b, b_conv_w, b_conv_b);
    // 3) x_proj -> (dt_low | B | C)
    sgemm<<<dim3(1, NT/128), 256>>>(xc0, f_xproj_w, dbc0, 64, DI, DI, nullptr, 0);
    sgemm<<<dim3(1, NT/128), 256>>>(xc1, b_xproj_w, dbc1, 64, DI, DI, nullptr, 0);
    // 4) dt_proj + softplus (A strided: lda=64, K=32)
    sgemm<<<dim3(DI/64, NT/128), 256>>>(dbc0, f_dt_w, dt0, DI, 32, 64, f_dt_b, 1);
    sgemm<<<dim3(DI/64, NT/128), 256>>>(dbc1, b_dt_w, dt1, DI, 32, 64, b_dt_b, 1);
    // 5) selective scan (fwd+bwd concurrently), fused +x*D and *silu(z)
    scan_kernel<<<dim3(64, 2), 128>>>(f_A_log, f_D, b_A_log, b_D);
    // 6) out_proj
    sgemm<<<dim3(DM/64, NT/128), 256>>>(ys0, f_out_w, mp0, DM, DI, DI, nullptr, 0);
    sgemm<<<dim3(DM/64, NT/128), 256>>>(ys1, b_out_w, mp1, DM, DI, DI, nullptr, 0);
    // 7) two residual LNs + average
    ln_mid<<<NT/8, 256>>>(x, ln_f_g, ln_f_b, ln_b_g, ln_b_b);
    // 8) FFN
    sgemm<<<dim3(DFF/64, NT/128), 256>>>(p_h,  ffn_w1, p_mid, DFF, DM,  DM,  ffn_b1, 2);
    sgemm<<<dim3(DM/64,  NT/128), 256>>>(p_mid, ffn_w2, p_ff2, DM,  DFF, DFF, ffn_b2, 3);
    // 9) final LN -> output
    ln_fin<<<NT/8, 256>>>((float*)d_out, ln_ff_g, ln_ff_b);
}

// round 3
// speedup vs baseline: 1.8211x; 1.8211x over previous
#include <cuda_runtime.h>
#include <math.h>
#include <stdint.h>

#define BB 8
#define LL 4096
#define DM 512
#define DI 1024
#define DXZ 2048
#define NST 16
#define DFF 2048
#define NT (BB*LL)   // 32768 tokens

// ---------------- scratch (allocation-free: __device__ globals) ----------------
__device__ float g_xz [2][(size_t)NT*DXZ];   // in_proj out (xi | z)
__device__ float g_xc [2][(size_t)NT*DI];    // conv+silu out
__device__ float g_dbc[2][(size_t)NT*64];    // x_proj out (dt_low | B | C)
__device__ float g_dt [2][(size_t)NT*DI];    // softplus(dt)
__device__ float g_ys [2][(size_t)NT*DI];    // scan out * silu(z)
__device__ float g_mp [2][(size_t)NT*DM];    // mamba out_proj
__device__ float g_h  [(size_t)NT*DM];       // 0.5*(LN_f + LN_b)
__device__ float g_mid[(size_t)NT*DFF];      // FFN hidden
__device__ float g_ff2[(size_t)NT*DM];       // FFN out

// ---------------- math helpers ----------------
__device__ __forceinline__ float sigmoidf_(float x){ return 1.f/(1.f+__expf(-x)); }
__device__ __forceinline__ float softplusf_(float x){ return fmaxf(x,0.f) + log1pf(__expf(-fabsf(x))); }
__device__ __forceinline__ float geluf_(float x){
    float x3 = x*x*x;
    return 0.5f*x*(1.f + tanhf(0.7978845608028654f*(x + 0.044715f*x3)));
}
__device__ __forceinline__ float warp_sum(float v){
    #pragma unroll
    for (int o=16;o>0;o>>=1) v += __shfl_xor_sync(0xffffffffu, v, o);
    return v;
}

// ---------------- tf32 helpers ----------------
__device__ __forceinline__ void split_tf32(float x, uint32_t& hi, uint32_t& lo){
    uint32_t h; asm("cvt.rna.tf32.f32 %0, %1;" : "=r"(h) : "f"(x));
    float r = x - __uint_as_float(h);
    uint32_t l; asm("cvt.rna.tf32.f32 %0, %1;" : "=r"(l) : "f"(r));
    hi = h; lo = l;
}
__device__ __forceinline__ void mma8(float* c, const uint32_t* a, uint32_t b0, uint32_t b1){
    asm volatile("mma.sync.aligned.m16n8k8.row.col.f32.tf32.tf32.f32 "
        "{%0,%1,%2,%3}, {%4,%5,%6,%7}, {%8,%9}, {%0,%1,%2,%3};"
        : "+f"(c[0]), "+f"(c[1]), "+f"(c[2]), "+f"(c[3])
        : "r"(a[0]), "r"(a[1]), "r"(a[2]), "r"(a[3]), "r"(b0), "r"(b1));
}
__device__ __forceinline__ void cp16(void* s, const void* g){
    uint32_t sa = (uint32_t)__cvta_generic_to_shared(s);
    asm volatile("cp.async.cg.shared.global [%0], [%1], 16;\n" :: "r"(sa), "l"(g));
}
__device__ __forceinline__ void cp_commit(){ asm volatile("cp.async.commit_group;\n" ::: "memory"); }
__device__ __forceinline__ void cp_wait1(){ asm volatile("cp.async.wait_group 1;\n" ::: "memory"); }

// ---------------- tensor-core GEMM (3xTF32): C[M,N] = A[M,K](lda) @ B[N,K]^T ----------------
// epi: 0 none, 1 softplus(+bias), 2 gelu(+bias), 3 +bias
// Requires: M%128==0, N%128==0, K%16==0, lda%4==0, K%4==0
#define TSTRIDE 20   // 16 + 4 pad (words): bank = (20*r + k) mod 32 covers all 32 banks
__global__ void __launch_bounds__(256,2)
tgemm(const float* __restrict__ A, const float* __restrict__ B, float* __restrict__ C,
      int N, int K, int lda, const float* __restrict__ bias, int epi)
{
    __shared__ float As[2][128*TSTRIDE];
    __shared__ float Bs[2][128*TSTRIDE];
    const int tid  = threadIdx.x;
    const int lane = tid & 31, warp = tid >> 5;
    const int wr = warp & 1;   // m-warp (0..1), 64 rows each
    const int wc = warp >> 1;  // n-warp (0..3), 32 cols each
    const int m0 = blockIdx.y*128, n0 = blockIdx.x*128;

    // global->smem: each thread 2 float4 per tile (A and B)
    const int lrow = tid >> 2;          // 0..63
    const int lcol = (tid & 3) * 4;     // 0,4,8,12
    const float* Ag = A + (size_t)(m0 + lrow)*lda + lcol;
    const float* Bg = B + (size_t)(n0 + lrow)*K   + lcol;

    const int niter = K / 16;

    // prologue: issue tiles 0 and 1
    {
        cp16(&As[0][lrow*TSTRIDE + lcol],      Ag);
        cp16(&As[0][(lrow+64)*TSTRIDE + lcol], Ag + (size_t)64*lda);
        cp16(&Bs[0][lrow*TSTRIDE + lcol],      Bg);
        cp16(&Bs[0][(lrow+64)*TSTRIDE + lcol], Bg + (size_t)64*K);
        cp_commit();
        if (niter > 1) {
            cp16(&As[1][lrow*TSTRIDE + lcol],      Ag + 16);
            cp16(&As[1][(lrow+64)*TSTRIDE + lcol], Ag + (size_t)64*lda + 16);
            cp16(&Bs[1][lrow*TSTRIDE + lcol],      Bg + 16);
            cp16(&Bs[1][(lrow+64)*TSTRIDE + lcol], Bg + (size_t)64*K + 16);
        }
        cp_commit();
    }

    float acc[4][4][4];
    #pragma unroll
    for (int i=0;i<4;i++)
        #pragma unroll
        for (int j=0;j<4;j++)
            #pragma unroll
            for (int q=0;q<4;q++) acc[i][j][q]=0.f;

    for (int it=0; it<niter; it++) {
        cp_wait1();
        __syncthreads();
        const int b = it & 1;
        const float* __restrict__ as = As[b];
        const float* __restrict__ bs = Bs[b];
        #pragma unroll
        for (int ks=0; ks<16; ks+=8) {
            const int kk = ks + (lane & 3);
            uint32_t Ah[4][4], Al[4][4];
            #pragma unroll
            for (int mt=0; mt<4; mt++) {
                const int mr = wr*64 + mt*16 + (lane>>2);
                split_tf32(as[mr*TSTRIDE + kk],        Ah[mt][0], Al[mt][0]);
                split_tf32(as[(mr+8)*TSTRIDE + kk],    Ah[mt][1], Al[mt][1]);
                split_tf32(as[mr*TSTRIDE + kk + 4],    Ah[mt][2], Al[mt][2]);
                split_tf32(as[(mr+8)*TSTRIDE + kk + 4],Ah[mt][3], Al[mt][3]);
            }
            #pragma unroll
            for (int nt=0; nt<4; nt++) {
                const int nc = wc*32 + nt*8 + (lane>>2);
                uint32_t bh0, bl0, bh1, bl1;
                split_tf32(bs[nc*TSTRIDE + kk],     bh0, bl0);
                split_tf32(bs[nc*TSTRIDE + kk + 4], bh1, bl1);
                #pragma unroll
                for (int mt=0; mt<4; mt++) {
                    mma8(acc[mt][nt], Ah[mt], bh0, bh1);
                    mma8(acc[mt][nt], Al[mt], bh0, bh1);
                    mma8(acc[mt][nt], Ah[mt], bl0, bl1);
                }
            }
        }
        __syncthreads();
        if (it + 2 < niter) {
            const int k2 = (it+2)*16;
            cp16(&As[b][lrow*TSTRIDE + lcol],      Ag + k2);
            cp16(&As[b][(lrow+64)*TSTRIDE + lcol], Ag + (size_t)64*lda + k2);
            cp16(&Bs[b][lrow*TSTRIDE + lcol],      Bg + k2);
            cp16(&Bs[b][(lrow+64)*TSTRIDE + lcol], Bg + (size_t)64*K + k2);
        }
        cp_commit();
    }

    // epilogue
    #pragma unroll
    for (int mt=0; mt<4; mt++) {
        const int r0 = m0 + wr*64 + mt*16 + (lane>>2);
        #pragma unroll
        for (int nt=0; nt<4; nt++) {
            const int cb = n0 + wc*32 + nt*8 + (lane&3)*2;
            float v0=acc[mt][nt][0], v1=acc[mt][nt][1], v2=acc[mt][nt][2], v3=acc[mt][nt][3];
            if (epi) {
                const float b0 = bias[cb], b1 = bias[cb+1];
                if (epi==1){ v0=softplusf_(v0+b0); v1=softplusf_(v1+b1); v2=softplusf_(v2+b0); v3=softplusf_(v3+b1); }
                else if (epi==2){ v0=geluf_(v0+b0); v1=geluf_(v1+b1); v2=geluf_(v2+b0); v3=geluf_(v3+b1); }
                else { v0+=b0; v1+=b1; v2+=b0; v3+=b1; }
            }
            *(float2*)(C + (size_t)r0*N + cb)     = make_float2(v0, v1);
            *(float2*)(C + (size_t)(r0+8)*N + cb) = make_float2(v2, v3);
        }
    }
}

// ---------------- fp32 SGEMM (kept for x_proj: N=64) ----------------
__global__ void __launch_bounds__(256,2)
sgemm(const float* __restrict__ A, const float* __restrict__ B, float* __restrict__ C,
      int N, int K, int lda, const float* __restrict__ bias, int epi)
{
    __shared__ float As[8][132];
    __shared__ float Bs[8][68];
    const int tid = threadIdx.x;
    const int m0 = blockIdx.y*128, n0 = blockIdx.x*64;
    const int tx = tid & 15, ty = tid >> 4;
    const int arow = tid >> 1,          ak = (tid & 1)*4;
    const int brow = (tid & 127) >> 1,  bk = (tid & 1)*4;

    float acc[8][4];
    #pragma unroll
    for (int i=0;i<8;i++)
        #pragma unroll
        for (int j=0;j<4;j++) acc[i][j]=0.f;

    const float* Ap = A + (size_t)(m0+arow)*lda + ak;
    const float* Bp = B + (size_t)(n0+brow)*K  + bk;

    for (int k0=0;k0<K;k0+=8) {
        float4 av = *(const float4*)(Ap + k0);
        float4 bv = make_float4(0.f,0.f,0.f,0.f);
        if (tid < 128) bv = *(const float4*)(Bp + k0);
        __syncthreads();
        As[ak+0][arow]=av.x; As[ak+1][arow]=av.y; As[ak+2][arow]=av.z; As[ak+3][arow]=av.w;
        if (tid < 128) { Bs[bk+0][brow]=bv.x; Bs[bk+1][brow]=bv.y; Bs[bk+2][brow]=bv.z; Bs[bk+3][brow]=bv.w; }
        __syncthreads();
        #pragma unroll
        for (int kk=0; kk<8; kk++) {
            float a[8], b[4];
            *(float4*)(a  ) = *(const float4*)(&As[kk][ty*8  ]);
            *(float4*)(a+4) = *(const float4*)(&As[kk][ty*8+4]);
            *(float4*)(b  ) = *(const float4*)(&Bs[kk][tx*4  ]);
            #pragma unroll
            for (int i=0;i<8;i++)
                #pragma unroll
                for (int j=0;j<4;j++) acc[i][j] = fmaf(a[i], b[j], acc[i][j]);
        }
    }

    #pragma unroll
    for (int i=0;i<8;i++) {
        int m = m0 + ty*8 + i;
        float4 o;
        float* op = (float*)&o;
        #pragma unroll
        for (int j=0;j<4;j++) {
            int n = n0 + tx*4 + j;
            float v = acc[i][j];
            if (epi==1)      v = softplusf_(v + bias[n]);
            else if (epi==2) v = geluf_(v + bias[n]);
            else if (epi==3) v = v + bias[n];
            op[j] = v;
        }
        *(float4*)(C + (size_t)m*N + n0 + tx*4) = o;
    }
}

// ---------------- depthwise causal/anti-causal conv(k=4) + SiLU ----------------
__global__ void conv_silu(const float* __restrict__ fw, const float* __restrict__ fb,
                          const float* __restrict__ bw, const float* __restrict__ bb)
{
    int dir = blockIdx.y;
    int idx = blockIdx.x*blockDim.x + threadIdx.x;     // over NT*DI
    int d = idx & (DI-1);
    int t = idx >> 10;
    int b = t >> 12, l = t & (LL-1);
    const float* w  = dir ? bw : fw;
    const float* cb = dir ? bb : fb;
    const float* xz = g_xz[dir];
    float acc = cb[d];
    if (!dir) {
        #pragma unroll
        for (int j=0;j<4;j++) {
            int l2 = l-3+j;
            if (l2 >= 0) acc = fmaf(w[d*4+j], xz[((size_t)(b*LL+l2))*DXZ + d], acc);
        }
    } else {
        #pragma unroll
        for (int j=0;j<4;j++) {
            int l2 = l+3-j;
            if (l2 < LL) acc = fmaf(w[d*4+j], xz[((size_t)(b*LL+l2))*DXZ + d], acc);
        }
    }
    g_xc[dir][idx] = acc * sigmoidf_(acc);
}

// ---------------- selective scan: 1 thread per (b,d), 16 states in regs ----------------
__global__ void scan_kernel(const float* __restrict__ AlF, const float* __restrict__ DF,
                            const float* __restrict__ AlB, const float* __restrict__ DB)
{
    int dir = blockIdx.y;
    int gid = blockIdx.x*blockDim.x + threadIdx.x;   // 0..8191
    int b = gid >> 10, d = gid & (DI-1);
    const float* Alog = dir ? AlB : AlF;
    const float* Dp   = dir ? DB  : DF;

    float a[NST];
    #pragma unroll
    for (int n=0;n<NST;n++) a[n] = -__expf(Alog[d*NST+n]);
    float Dd = Dp[d];
    float h[NST];
    #pragma unroll
    for (int n=0;n<NST;n++) h[n] = 0.f;

    const float* dtb = g_dt[dir];
    const float* xcb = g_xc[dir];
    const float* zb  = g_xz[dir];
    const float* bcb = g_dbc[dir];
    float*       yb  = g_ys[dir];

    for (int s=0;s<LL;s++) {
        int l = dir ? (LL-1-s) : s;
        size_t t = (size_t)b*LL + l;
        float dtv = dtb[t*DI + d];
        float xv  = xcb[t*DI + d];
        float zv  = zb [t*DXZ + DI + d];
        const float* bc = bcb + t*64;
        float dx = dtv*xv;
        float y = 0.f;
        #pragma unroll
        for (int n=0;n<NST;n++) {
            float e = __expf(dtv*a[n]);
            h[n] = fmaf(e, h[n], dx*bc[32+n]);
            y = fmaf(h[n], bc[48+n], y);
        }
        y = fmaf(xv, Dd, y);
        y *= zv * sigmoidf_(zv);
        yb[t*DI + d] = y;
    }
}

// ---------------- fused: out_f=LN(x+mf), out_b=LN(x+mb), h=0.5*(of+ob) ----------------
__global__ void ln_mid(const float* __restrict__ x,
                       const float* __restrict__ gf, const float* __restrict__ bf,
                       const float* __restrict__ gb, const float* __restrict__ bb)
{
    int warp = threadIdx.x >> 5, lane = threadIdx.x & 31;
    int row = blockIdx.x*8 + warp;
    const float* xr  = x        + (size_t)row*DM;
    const float* mfr = g_mp[0]  + (size_t)row*DM;
    const float* mbr = g_mp[1]  + (size_t)row*DM;
    float u[16], v[16];
    float su=0.f, sv=0.f, squ=0.f, sqv=0.f;
    #pragma unroll
    for (int i=0;i<16;i++) {
        int c = lane + i*32;
        float xv = xr[c];
        u[i] = xv + mfr[c]; v[i] = xv + mbr[c];
        su += u[i]; sv += v[i];
        squ = fmaf(u[i],u[i],squ); sqv = fmaf(v[i],v[i],sqv);
    }
    su = warp_sum(su); sv = warp_sum(sv);
    squ = warp_sum(squ); sqv = warp_sum(sqv);
    float muu = su*(1.f/DM), mub = sv*(1.f/DM);
    float ru = rsqrtf(squ*(1.f/DM) - muu*muu + 1e-5f);
    float rv = rsqrtf(sqv*(1.f/DM) - mub*mub + 1e-5f);
    #pragma unroll
    for (int i=0;i<16;i++) {
        int c = lane + i*32;
        float of = (u[i]-muu)*ru*gf[c] + bf[c];
        float ob = (v[i]-mub)*rv*gb[c] + bb[c];
        g_h[(size_t)row*DM + c] = 0.5f*(of + ob);
    }
}

// ---------------- final: out = LN(h + ff) ----------------
__global__ void ln_fin(float* __restrict__ out,
                       const float* __restrict__ g, const float* __restrict__ bta)
{
    int warp = threadIdx.x >> 5, lane = threadIdx.x & 31;
    int row = blockIdx.x*8 + warp;
    const float* hr = g_h  + (size_t)row*DM;
    const float* fr = g_ff2 + (size_t)row*DM;
    float u[16];
    float su=0.f, squ=0.f;
    #pragma unroll
    for (int i=0;i<16;i++) {
        int c = lane + i*32;
        u[i] = hr[c] + fr[c];
        su += u[i]; squ = fmaf(u[i],u[i],squ);
    }
    su = warp_sum(su); squ = warp_sum(squ);
    float mu = su*(1.f/DM);
    float r  = rsqrtf(squ*(1.f/DM) - mu*mu + 1e-5f);
    #pragma unroll
    for (int i=0;i<16;i++) {
        int c = lane + i*32;
        out[(size_t)row*DM + c] = (u[i]-mu)*r*g[c] + bta[c];
    }
}

// ---------------- host ----------------
extern "C" void kernel_launch(void* const* d_in, const int* in_sizes, int n_in,
                              void* d_out, int out_size)
{
    const float* x        = (const float*)d_in[0];
    const float* f_in_w   = (const float*)d_in[1];
    const float* f_conv_w = (const float*)d_in[2];
    const float* f_conv_b = (const float*)d_in[3];
    const float* f_xproj_w= (const float*)d_in[4];
    const float* f_dt_w   = (const float*)d_in[5];
    const float* f_dt_b   = (const float*)d_in[6];
    const float* f_A_log  = (const float*)d_in[7];
    const float* f_D      = (const float*)d_in[8];
    const float* f_out_w  = (const float*)d_in[9];
    const float* b_in_w   = (const float*)d_in[10];
    const float* b_conv_w = (const float*)d_in[11];
    const float* b_conv_b = (const float*)d_in[12];
    const float* b_xproj_w= (const float*)d_in[13];
    const float* b_dt_w   = (const float*)d_in[14];
    const float* b_dt_b   = (const float*)d_in[15];
    const float* b_A_log  = (const float*)d_in[16];
    const float* b_D      = (const float*)d_in[17];
    const float* b_out_w  = (const float*)d_in[18];
    const float* ln_f_g   = (const float*)d_in[19];
    const float* ln_f_b   = (const float*)d_in[20];
    const float* ln_b_g   = (const float*)d_in[21];
    const float* ln_b_b   = (const float*)d_in[22];
    const float* ln_ff_g  = (const float*)d_in[23];
    const float* ln_ff_b  = (const float*)d_in[24];
    const float* ffn_w1   = (const float*)d_in[25];
    const float* ffn_b1   = (const float*)d_in[26];
    const float* ffn_w2   = (const float*)d_in[27];
    const float* ffn_b2   = (const float*)d_in[28];

    float *p_xz, *p_xc, *p_dbc, *p_dt, *p_ys, *p_mp, *p_h, *p_mid, *p_ff2;
    cudaGetSymbolAddress((void**)&p_xz , g_xz );
    cudaGetSymbolAddress((void**)&p_xc , g_xc );
    cudaGetSymbolAddress((void**)&p_dbc, g_dbc);
    cudaGetSymbolAddress((void**)&p_dt , g_dt );
    cudaGetSymbolAddress((void**)&p_ys , g_ys );
    cudaGetSymbolAddress((void**)&p_mp , g_mp );
    cudaGetSymbolAddress((void**)&p_h  , g_h  );
    cudaGetSymbolAddress((void**)&p_mid, g_mid);
    cudaGetSymbolAddress((void**)&p_ff2, g_ff2);
    float* xz0 = p_xz;            float* xz1 = p_xz  + (size_t)NT*DXZ;
    float* xc0 = p_xc;            float* xc1 = p_xc  + (size_t)NT*DI;
    float* dbc0= p_dbc;           float* dbc1= p_dbc + (size_t)NT*64;
    float* dt0 = p_dt;            float* dt1 = p_dt  + (size_t)NT*DI;
    float* ys0 = p_ys;            float* ys1 = p_ys  + (size_t)NT*DI;
    float* mp0 = p_mp;            float* mp1 = p_mp  + (size_t)NT*DM;

    // 1) in_proj (tensor cores; flip folded into conv/scan)
    tgemm<<<dim3(DXZ/128, NT/128), 256>>>(x, f_in_w, xz0, DXZ, DM, DM, nullptr, 0);
    tgemm<<<dim3(DXZ/128, NT/128), 256>>>(x, b_in_w, xz1, DXZ, DM, DM, nullptr, 0);
    // 2) depthwise conv + SiLU
    conv_silu<<<dim3((NT*DI)/256, 2), 256>>>(f_conv_w, f_conv_b, b_conv_w, b_conv_b);
    // 3) x_proj -> (dt_low | B | C): N=64, keep fp32 path
    sgemm<<<dim3(1, NT/128), 256>>>(xc0, f_xproj_w, dbc0, 64, DI, DI, nullptr, 0);
    sgemm<<<dim3(1, NT/128), 256>>>(xc1, b_xproj_w, dbc1, 64, DI, DI, nullptr, 0);
    // 4) dt_proj + softplus (A strided: lda=64, K=32)
    tgemm<<<dim3(DI/128, NT/128), 256>>>(dbc0, f_dt_w, dt0, DI, 32, 64, f_dt_b, 1);
    tgemm<<<dim3(DI/128, NT/128), 256>>>(dbc1, b_dt_w, dt1, DI, 32, 64, b_dt_b, 1);
    // 5) selective scan (fwd+bwd concurrently), fused +x*D and *silu(z)
    scan_kernel<<<dim3(64, 2), 128>>>(f_A_log, f_D, b_A_log, b_D);
    // 6) out_proj
    tgemm<<<dim3(DM/128, NT/128), 256>>>(ys0, f_out_w, mp0, DM, DI, DI, nullptr, 0);
    tgemm<<<dim3(DM/128, NT/128), 256>>>(ys1, b_out_w, mp1, DM, DI, DI, nullptr, 0);
    // 7) two residual LNs + average
    ln_mid<<<NT/8, 256>>>(x, ln_f_g, ln_f_b, ln_b_g, ln_b_b);
    // 8) FFN
    tgemm<<<dim3(DFF/128, NT/128), 256>>>(p_h,   ffn_w1, p_mid, DFF, DM,  DM,  ffn_b1, 2);
    tgemm<<<dim3(DM/128,  NT/128), 256>>>(p_mid, ffn_w2, p_ff2, DM,  DFF, DFF, ffn_b2, 3);
    // 9) final LN -> output
    ln_fin<<<NT/8, 256>>>((float*)d_out, ln_ff_g, ln_ff_b);
}